// round 15
// baseline (speedup 1.0000x reference)
#include <cuda_runtime.h>
#include <cstddef>

#define NB   8
#define NQ   100
#define SH   128
#define SW   128
#define OH   512
#define OW   512
#define QPI  4            // queries per iteration
#define NIT  (NQ / QPI)   // 25

__device__ __forceinline__ float fast_tanh(float x) {
    float r;
    asm("tanh.approx.f32 %0, %1;" : "=f"(r) : "f"(x));
    return r;
}

// bar.sync with a named barrier: 128 threads (one ph-group = 4 warps).
__device__ __forceinline__ void group_bar(int id) {
    asm volatile("bar.sync %0, 128;" :: "r"(id) : "memory");
}

// Grid: (128 row-blocks k, 8 batches). Block: 512 threads, 3 CTAs/SM.
// R14 pipeline, but the block-wide __syncthreads in the main loop is replaced
// by NAMED BARRIERS per ph-group (4 warps / 128 threads each): vrow[.][e][ph]
// is produced and consumed entirely within one ph-group, so the 4 groups are
// independent pipelines — barrier skew no longer couples all 16 warps.
__global__ __launch_bounds__(512, 3)
void m2f_fused_kernel(const float* __restrict__ cls,
                      const float* __restrict__ masks,
                      float* __restrict__ out)
{
    const int k = blockIdx.x;
    const int b = blockIdx.y;
    const int t = threadIdx.x;

    __shared__ __align__(16) float  vrow[2][QPI][4][SW];  // halved vertical lerps
    __shared__ __align__(16) float2 wts[NQ];              // pre-halved weights
    __shared__ float2 wsumg[4];                           // per-group weight sums

    // ---- per-CTA class softmax (halved) ----
    if (t < NQ) {
        const float* p = cls + ((size_t)b * NQ + t) * 3;
        float x0 = p[0], x1 = p[1], x2 = p[2];
        float m  = fmaxf(x0, fmaxf(x1, x2));
        float e0 = __expf(x0 - m), e1 = __expf(x1 - m), e2 = __expf(x2 - m);
        float inv = 0.5f / (e0 + e1 + e2);
        wts[t] = make_float2(e0 * inv, e1 * inv);
    }

    // clamped source rows
    const int r0 = (k == 0)      ? 0        : (k - 1);
    const int r2 = (k == SH - 1) ? (SH - 1) : (k + 1);
    const float* mb = masks + (size_t)b * NQ * SH * SW;
    const size_t qstride = (size_t)SH * SW;     // floats per query
    const size_t qf4     = qstride / 4;         // float4s per query

    // shared role keys: ph = t>>7 (row phase / group id), kx = t&127
    const int ph  = t >> 7;
    const int kx  = t & 127;
    const float vf = (ph == 0) ? 0.625f : (ph == 1) ? 0.875f
                   : (ph == 2) ? 0.125f : 0.375f;
    const int rowA = (ph < 2) ? r0 : k;
    const int rowB = (ph < 2) ? k  : r2;
    const int kxm = (kx == 0)      ? 0        : kx - 1;
    const int kxp = (kx == SW - 1) ? (SW - 1) : kx + 1;

    // vertical role: warp w -> (e = w&3, group ph = w>>2); lane -> 4-col group
    const int wid = t >> 5;
    const int ev  = wid & 3;
    const int c4g = t & 31;
    const float4* pA = reinterpret_cast<const float4*>(
        mb + (size_t)ev * qstride + (size_t)rowA * SW) + c4g;
    const float4* pB = reinterpret_cast<const float4*>(
        mb + (size_t)ev * qstride + (size_t)rowB * SW) + c4g;

    // ---- prologue: vertical quad 0 -> vrow[0] ----
    {
        float4 la = __ldg(pA);
        float4 lb = __ldg(pB);
        float4 r;
        r.x = 0.5f * fmaf(vf, lb.x - la.x, la.x);
        r.y = 0.5f * fmaf(vf, lb.y - la.y, la.y);
        r.z = 0.5f * fmaf(vf, lb.z - la.z, la.z);
        r.w = 0.5f * fmaf(vf, lb.w - la.w, la.w);
        *reinterpret_cast<float4*>(&vrow[0][ev][ph][4 * c4g]) = r;
        pA += QPI * qf4;
        pB += QPI * qf4;
    }

    __syncthreads();   // wts + vrow[0] published block-wide (last full barrier)

    // per-group weight sum by the group's leader warp (wid = 4*ph).
    // Ordered for the group's readers by the group's own named barriers.
    if ((wid & 3) == 0) {
        const int lane = t & 31;
        float sx = 0.f, sy = 0.f;
        for (int q = lane; q < NQ; q += 32) { sx += wts[q].x; sy += wts[q].y; }
        #pragma unroll
        for (int o = 16; o > 0; o >>= 1) {
            sx += __shfl_down_sync(0xFFFFFFFFu, sx, o);
            sy += __shfl_down_sync(0xFFFFFFFFu, sy, o);
        }
        if (lane == 0) wsumg[wid >> 2] = make_float2(sx, sy);
    }

    float acc0[4] = {0.f,0.f,0.f,0.f};
    float acc1[4] = {0.f,0.f,0.f,0.f};
    const float4* wv = reinterpret_cast<const float4*>(wts);
    const int bar_id = ph + 1;   // named barriers 1..4 (0 left for syncthreads)

    #pragma unroll 2
    for (int j = 0; j < NIT; j++) {
        const int bs = j & 1;
        const int nb = bs ^ 1;

        // issue LDG for quad j+1 first (hidden under horizontal compute)
        float4 la, lb;
        const bool dv = (j + 1 < NIT);
        if (dv) {
            la = __ldg(pA);
            lb = __ldg(pB);
        }

        // horizontal: quad j from vrow[bs] (reads stay within this ph-group)
        {
            const float4 wA = wv[2*j];
            const float4 wB = wv[2*j+1];
            const float wxa[4] = {wA.x, wA.z, wB.x, wB.z};
            const float wya[4] = {wA.y, wA.w, wB.y, wB.w};

            #pragma unroll
            for (int e = 0; e < QPI; e++) {
                const float vL = vrow[bs][e][ph][kxm];
                const float vM = vrow[bs][e][ph][kx];
                const float vR = vrow[bs][e][ph][kxp];
                const float dl = vM - vL;
                const float dr = vR - vM;

                float t0 = fast_tanh(fmaf(0.625f, dl, vL));
                float t1 = fast_tanh(fmaf(0.875f, dl, vL));
                float t2 = fast_tanh(fmaf(0.125f, dr, vM));
                float t3 = fast_tanh(fmaf(0.375f, dr, vM));

                const float wx = wxa[e], wy = wya[e];
                acc0[0] = fmaf(wx, t0, acc0[0]);
                acc0[1] = fmaf(wx, t1, acc0[1]);
                acc0[2] = fmaf(wx, t2, acc0[2]);
                acc0[3] = fmaf(wx, t3, acc0[3]);
                acc1[0] = fmaf(wy, t0, acc1[0]);
                acc1[1] = fmaf(wy, t1, acc1[1]);
                acc1[2] = fmaf(wy, t2, acc1[2]);
                acc1[3] = fmaf(wy, t3, acc1[3]);
            }
        }

        // vertical: quad j+1 -> vrow[nb] (written only by this ph-group)
        if (dv) {
            float4 r;
            r.x = 0.5f * fmaf(vf, lb.x - la.x, la.x);
            r.y = 0.5f * fmaf(vf, lb.y - la.y, la.y);
            r.z = 0.5f * fmaf(vf, lb.z - la.z, la.z);
            r.w = 0.5f * fmaf(vf, lb.w - la.w, la.w);
            *reinterpret_cast<float4*>(&vrow[nb][ev][ph][4 * c4g]) = r;
            pA += QPI * qf4;
            pB += QPI * qf4;
        }
        group_bar(bar_id);   // only this ph-group's 4 warps
    }

    // out[b][c][4k+ph][4kx + 0..3] = acc + Sum(w/2)
    const float2 S = wsumg[ph];
    const int y = 4 * k + ph;
    float4 o0 = make_float4(acc0[0] + S.x, acc0[1] + S.x,
                            acc0[2] + S.x, acc0[3] + S.x);
    float4 o1 = make_float4(acc1[0] + S.y, acc1[1] + S.y,
                            acc1[2] + S.y, acc1[3] + S.y);
    const size_t base0 = (((size_t)b * 2 + 0) * OH + y) * OW + 4 * kx;
    const size_t base1 = (((size_t)b * 2 + 1) * OH + y) * OW + 4 * kx;
    *reinterpret_cast<float4*>(out + base0) = o0;
    *reinterpret_cast<float4*>(out + base1) = o1;
}

extern "C" void kernel_launch(void* const* d_in, const int* in_sizes, int n_in,
                              void* d_out, int out_size)
{
    const float* cls   = (const float*)d_in[0];  // [8,100,3]
    const float* masks = (const float*)d_in[1];  // [8,100,128,128]
    float*       out   = (float*)d_out;          // [8,2,512,512]

    dim3 grid(SH, NB);
    dim3 block(512);
    m2f_fused_kernel<<<grid, block>>>(cls, masks, out);
}